// round 6
// baseline (speedup 1.0000x reference)
#include <cuda_runtime.h>
#include <cuda_fp16.h>
#include <cstdint>

#define NUM_USERS 100000
#define NUM_ITEMS 50000
#define N_NODES   150000
#define EMB       64
#define BATCH     4096
#define MAX_EDGES 4800000

#define SCAN_BS   1024
#define SCAN_NB   ((N_NODES + SCAN_BS - 1) / SCAN_BS)   // 147

#define F8_SCALE    512.0f
#define F8_INVSCALE (1.0f / 512.0f)

// ---- static scratch (allocation-free) ----
__device__ int4  g_curH [(size_t)N_NODES * 8];   // emb fp16, then reused as l3
__device__ int4  g_l1H  [(size_t)N_NODES * 8];
__device__ int4  g_l2H  [(size_t)N_NODES * 8];
__device__ int2  g_l2F8 [(size_t)N_NODES * 8];   // l2 * 512 in e4m3
__device__ int2  g_edges[MAX_EDGES];             // {col, val_bits} sorted by row
__device__ int   g_count[N_NODES];               // zero on entry (BSS / re-zeroed by scan23)
__device__ int   g_rowptr[N_NODES + 1];
__device__ int   g_off[N_NODES];
__device__ int   g_blocksum[SCAN_NB];

static __device__ __forceinline__ unsigned h2bits(__half2 h) {
    return *reinterpret_cast<unsigned*>(&h);
}
static __device__ __forceinline__ unsigned short pack_e4m3x2(float lo, float hi) {
    unsigned short s;
    asm("cvt.rn.satfinite.e4m3x2.f32 %0, %1, %2;" : "=h"(s) : "f"(hi), "f"(lo));
    return s;
}
static __device__ __forceinline__ float2 unpack_e4m3x2(unsigned short s) {
    unsigned hb;
    asm("cvt.rn.f16x2.e4m3x2 %0, %1;" : "=r"(hb) : "h"(s));
    return __half22float2(*reinterpret_cast<__half2*>(&hb));
}

// ---------------------------------------------------------------------------
// fused init + histogram: curH = fp16(emb); histogram 4 edges/thread (ILP).
// g_count zero on entry: BSS at load; scan23 re-zeros after its last read.
// ---------------------------------------------------------------------------
__global__ void init_hist_kernel(const float4* __restrict__ uemb,
                                 const float4* __restrict__ iemb,
                                 uint2* __restrict__ curH,
                                 const int* __restrict__ rows,
                                 int n_edges)
{
    const int n4      = N_NODES * (EMB / 4);
    const int n4_user = NUM_USERS * (EMB / 4);
    int i = blockIdx.x * blockDim.x + threadIdx.x;
    if (i < n4) {
        float4 v = (i < n4_user) ? __ldg(uemb + i) : __ldg(iemb + i - n4_user);
        uint2 c;
        c.x = h2bits(__floats2half2_rn(v.x, v.y));
        c.y = h2bits(__floats2half2_rn(v.z, v.w));
        curH[i] = c;
    }
    int e = i * 4;
    if (e + 3 < n_edges) {
        int4 r = *reinterpret_cast<const int4*>(rows + e);
        atomicAdd(&g_count[r.x], 1);
        atomicAdd(&g_count[r.y], 1);
        atomicAdd(&g_count[r.z], 1);
        atomicAdd(&g_count[r.w], 1);
    } else if (e < n_edges) {
        for (int k = e; k < n_edges; k++) atomicAdd(&g_count[__ldg(rows + k)], 1);
    }
}

// ---------------------------------------------------------------------------
// scan1: per-block sums of g_count
// ---------------------------------------------------------------------------
__global__ void scan1_kernel()
{
    int idx = blockIdx.x * SCAN_BS + threadIdx.x;
    int c = (idx < N_NODES) ? g_count[idx] : 0;
    int lane = threadIdx.x & 31, wid = threadIdx.x >> 5;
    #pragma unroll
    for (int o = 16; o; o >>= 1) c += __shfl_down_sync(0xFFFFFFFFu, c, o);
    __shared__ int ws[32];
    if (lane == 0) ws[wid] = c;
    __syncthreads();
    if (wid == 0) {
        c = ws[lane];
        #pragma unroll
        for (int o = 16; o; o >>= 1) c += __shfl_down_sync(0xFFFFFFFFu, c, o);
        if (lane == 0) g_blocksum[blockIdx.x] = c;
    }
}

// ---------------------------------------------------------------------------
// scan23: redundant block-sum scan per block + local exclusive scan.
// Writes rowptr + off; re-zeros g_count for the next replay.
// ---------------------------------------------------------------------------
__global__ void scan23_kernel(int n_edges)
{
    __shared__ int bs[256];
    __shared__ int ws[32];

    int t = threadIdx.x;
    if (t < 256) bs[t] = (t < SCAN_NB) ? g_blocksum[t] : 0;
    __syncthreads();
    #pragma unroll
    for (int off = 1; off < 256; off <<= 1) {
        int x = 0;
        if (t < 256 && t >= off) x = bs[t - off];
        __syncthreads();
        if (t < 256) bs[t] += x;
        __syncthreads();
    }
    int blockoff = (blockIdx.x == 0) ? 0 : bs[blockIdx.x - 1];

    int idx = blockIdx.x * SCAN_BS + t;
    int c = (idx < N_NODES) ? g_count[idx] : 0;
    int lane = t & 31, wid = t >> 5;
    int v = c;
    #pragma unroll
    for (int o = 1; o < 32; o <<= 1) {
        int s = __shfl_up_sync(0xFFFFFFFFu, v, o);
        if (lane >= o) v += s;
    }
    if (lane == 31) ws[wid] = v;
    __syncthreads();
    if (wid == 0) {
        int orig = ws[lane];
        int s = orig;
        #pragma unroll
        for (int o = 1; o < 32; o <<= 1) {
            int x = __shfl_up_sync(0xFFFFFFFFu, s, o);
            if (lane >= o) s += x;
        }
        ws[lane] = s - orig;
    }
    __syncthreads();
    int excl = (v - c) + ws[wid] + blockoff;
    if (idx < N_NODES) {
        g_rowptr[idx] = excl;
        g_off[idx]    = excl;
        g_count[idx]  = 0;
    }
    if (idx == 0) g_rowptr[N_NODES] = n_edges;
}

// ---------------------------------------------------------------------------
// scatter: 4 edges per thread, vectorized input reads, 4 independent
// atomic+store chains (raises MLP on the latency-bound atomic path).
// ---------------------------------------------------------------------------
__global__ void scatter_kernel(const int* __restrict__ rows,
                               const int* __restrict__ cols,
                               const float* __restrict__ vals, int n)
{
    int e = (blockIdx.x * blockDim.x + threadIdx.x) * 4;
    if (e + 3 < n) {
        int4   r = *reinterpret_cast<const int4*>(rows + e);
        int4   c = *reinterpret_cast<const int4*>(cols + e);
        float4 v = *reinterpret_cast<const float4*>(vals + e);
        int p0 = atomicAdd(&g_off[r.x], 1);
        int p1 = atomicAdd(&g_off[r.y], 1);
        int p2 = atomicAdd(&g_off[r.z], 1);
        int p3 = atomicAdd(&g_off[r.w], 1);
        g_edges[p0] = make_int2(c.x, __float_as_int(v.x));
        g_edges[p1] = make_int2(c.y, __float_as_int(v.y));
        g_edges[p2] = make_int2(c.z, __float_as_int(v.z));
        g_edges[p3] = make_int2(c.w, __float_as_int(v.w));
    } else if (e < n) {
        for (int k = e; k < n; k++) {
            int pos = atomicAdd(&g_off[__ldg(rows + k)], 1);
            g_edges[pos] = make_int2(__ldg(cols + k), __float_as_int(__ldg(vals + k)));
        }
    }
}

// ---------------------------------------------------------------------------
// CSR SpMM, fp16 src: 8 lanes per row, lane owns 8 features.
// Optionally emits an e4m3 (x F8_SCALE) copy of the output for the next layer.
// ---------------------------------------------------------------------------
__global__ void spmm_h16_kernel(const int4* __restrict__ src,
                                int4* __restrict__ dst,
                                int2* __restrict__ dstF8)
{
    int t = blockIdx.x * blockDim.x + threadIdx.x;
    int g = t >> 3;
    int l = t & 7;
    if (g >= N_NODES) return;
    unsigned gmask = 0xFFu << (threadIdx.x & 24);

    int start = __ldg(&g_rowptr[g]);
    int end   = __ldg(&g_rowptr[g + 1]);

    float4 alo = make_float4(0.f, 0.f, 0.f, 0.f);
    float4 ahi = make_float4(0.f, 0.f, 0.f, 0.f);

    int base = start;
    for (; base + 8 <= end; base += 8) {
        int2 e = __ldg(&g_edges[base + l]);
        #pragma unroll
        for (int k = 0; k < 8; k++) {
            int   col = __shfl_sync(gmask, e.x, k, 8);
            float v   = __int_as_float(__shfl_sync(gmask, e.y, k, 8));
            int4 q = __ldg(&src[(size_t)col * 8 + l]);
            float2 f0 = __half22float2(*reinterpret_cast<__half2*>(&q.x));
            float2 f1 = __half22float2(*reinterpret_cast<__half2*>(&q.y));
            float2 f2 = __half22float2(*reinterpret_cast<__half2*>(&q.z));
            float2 f3 = __half22float2(*reinterpret_cast<__half2*>(&q.w));
            alo.x = fmaf(v, f0.x, alo.x); alo.y = fmaf(v, f0.y, alo.y);
            alo.z = fmaf(v, f1.x, alo.z); alo.w = fmaf(v, f1.y, alo.w);
            ahi.x = fmaf(v, f2.x, ahi.x); ahi.y = fmaf(v, f2.y, ahi.y);
            ahi.z = fmaf(v, f3.x, ahi.z); ahi.w = fmaf(v, f3.y, ahi.w);
        }
    }
    int rem = end - base;
    if (rem > 0) {
        int2 e = (l < rem) ? __ldg(&g_edges[base + l]) : make_int2(0, 0);
        for (int k = 0; k < rem; k++) {
            int   col = __shfl_sync(gmask, e.x, k, 8);
            float v   = __int_as_float(__shfl_sync(gmask, e.y, k, 8));
            int4 q = __ldg(&src[(size_t)col * 8 + l]);
            float2 f0 = __half22float2(*reinterpret_cast<__half2*>(&q.x));
            float2 f1 = __half22float2(*reinterpret_cast<__half2*>(&q.y));
            float2 f2 = __half22float2(*reinterpret_cast<__half2*>(&q.z));
            float2 f3 = __half22float2(*reinterpret_cast<__half2*>(&q.w));
            alo.x = fmaf(v, f0.x, alo.x); alo.y = fmaf(v, f0.y, alo.y);
            alo.z = fmaf(v, f1.x, alo.z); alo.w = fmaf(v, f1.y, alo.w);
            ahi.x = fmaf(v, f2.x, ahi.x); ahi.y = fmaf(v, f2.y, ahi.y);
            ahi.z = fmaf(v, f3.x, ahi.z); ahi.w = fmaf(v, f3.y, ahi.w);
        }
    }

    int4 o;
    o.x = h2bits(__floats2half2_rn(alo.x, alo.y));
    o.y = h2bits(__floats2half2_rn(alo.z, alo.w));
    o.z = h2bits(__floats2half2_rn(ahi.x, ahi.y));
    o.w = h2bits(__floats2half2_rn(ahi.z, ahi.w));
    dst[(size_t)g * 8 + l] = o;

    if (dstF8) {
        unsigned short s0 = pack_e4m3x2(alo.x * F8_SCALE, alo.y * F8_SCALE);
        unsigned short s1 = pack_e4m3x2(alo.z * F8_SCALE, alo.w * F8_SCALE);
        unsigned short s2 = pack_e4m3x2(ahi.x * F8_SCALE, ahi.y * F8_SCALE);
        unsigned short s3 = pack_e4m3x2(ahi.z * F8_SCALE, ahi.w * F8_SCALE);
        int2 p;
        p.x = (unsigned)s0 | ((unsigned)s1 << 16);
        p.y = (unsigned)s2 | ((unsigned)s3 << 16);
        dstF8[(size_t)g * 8 + l] = p;
    }
}

// ---------------------------------------------------------------------------
// CSR SpMM, e4m3 src (pre-scaled by F8_SCALE): 64B gathers, fp16 out.
// ---------------------------------------------------------------------------
__global__ void spmm_f8_kernel(const int2* __restrict__ srcF8,
                               int4* __restrict__ dst)
{
    int t = blockIdx.x * blockDim.x + threadIdx.x;
    int g = t >> 3;
    int l = t & 7;
    if (g >= N_NODES) return;
    unsigned gmask = 0xFFu << (threadIdx.x & 24);

    int start = __ldg(&g_rowptr[g]);
    int end   = __ldg(&g_rowptr[g + 1]);

    float4 alo = make_float4(0.f, 0.f, 0.f, 0.f);
    float4 ahi = make_float4(0.f, 0.f, 0.f, 0.f);

    int base = start;
    for (; base + 8 <= end; base += 8) {
        int2 e = __ldg(&g_edges[base + l]);
        #pragma unroll
        for (int k = 0; k < 8; k++) {
            int   col = __shfl_sync(gmask, e.x, k, 8);
            float v   = __int_as_float(__shfl_sync(gmask, e.y, k, 8));
            int2 q = __ldg(&srcF8[(size_t)col * 8 + l]);
            float2 f0 = unpack_e4m3x2((unsigned short)(q.x & 0xFFFF));
            float2 f1 = unpack_e4m3x2((unsigned short)((unsigned)q.x >> 16));
            float2 f2 = unpack_e4m3x2((unsigned short)(q.y & 0xFFFF));
            float2 f3 = unpack_e4m3x2((unsigned short)((unsigned)q.y >> 16));
            alo.x = fmaf(v, f0.x, alo.x); alo.y = fmaf(v, f0.y, alo.y);
            alo.z = fmaf(v, f1.x, alo.z); alo.w = fmaf(v, f1.y, alo.w);
            ahi.x = fmaf(v, f2.x, ahi.x); ahi.y = fmaf(v, f2.y, ahi.y);
            ahi.z = fmaf(v, f3.x, ahi.z); ahi.w = fmaf(v, f3.y, ahi.w);
        }
    }
    int rem = end - base;
    if (rem > 0) {
        int2 e = (l < rem) ? __ldg(&g_edges[base + l]) : make_int2(0, 0);
        for (int k = 0; k < rem; k++) {
            int   col = __shfl_sync(gmask, e.x, k, 8);
            float v   = __int_as_float(__shfl_sync(gmask, e.y, k, 8));
            int2 q = __ldg(&srcF8[(size_t)col * 8 + l]);
            float2 f0 = unpack_e4m3x2((unsigned short)(q.x & 0xFFFF));
            float2 f1 = unpack_e4m3x2((unsigned short)((unsigned)q.x >> 16));
            float2 f2 = unpack_e4m3x2((unsigned short)(q.y & 0xFFFF));
            float2 f3 = unpack_e4m3x2((unsigned short)((unsigned)q.y >> 16));
            alo.x = fmaf(v, f0.x, alo.x); alo.y = fmaf(v, f0.y, alo.y);
            alo.z = fmaf(v, f1.x, alo.z); alo.w = fmaf(v, f1.y, alo.w);
            ahi.x = fmaf(v, f2.x, ahi.x); ahi.y = fmaf(v, f2.y, ahi.y);
            ahi.z = fmaf(v, f3.x, ahi.z); ahi.w = fmaf(v, f3.y, ahi.w);
        }
    }

    alo.x *= F8_INVSCALE; alo.y *= F8_INVSCALE; alo.z *= F8_INVSCALE; alo.w *= F8_INVSCALE;
    ahi.x *= F8_INVSCALE; ahi.y *= F8_INVSCALE; ahi.z *= F8_INVSCALE; ahi.w *= F8_INVSCALE;

    int4 o;
    o.x = h2bits(__floats2half2_rn(alo.x, alo.y));
    o.y = h2bits(__floats2half2_rn(alo.z, alo.w));
    o.z = h2bits(__floats2half2_rn(ahi.x, ahi.y));
    o.w = h2bits(__floats2half2_rn(ahi.z, ahi.w));
    dst[(size_t)g * 8 + l] = o;
}

// ---------------------------------------------------------------------------
// scoring: one warp per batch element; exact fp32 emb + fp16 layer terms.
// ---------------------------------------------------------------------------
__global__ void score_kernel(const int* __restrict__ users,
                             const int* __restrict__ pos_items,
                             const int* __restrict__ neg_items,
                             const float2* __restrict__ uemb,
                             const float2* __restrict__ iemb,
                             const __half2* __restrict__ l1,
                             const __half2* __restrict__ l2,
                             const __half2* __restrict__ l3,
                             float* __restrict__ out,
                             int batch)
{
    int w = (blockIdx.x * blockDim.x + threadIdx.x) >> 5;
    int l = threadIdx.x & 31;
    if (w >= batch) return;

    int u  = __ldg(users + w);
    int pi = __ldg(pos_items + w);
    int ni = __ldg(neg_items + w);

    size_t uoff = (size_t)u * 32 + l;
    size_t poff = (size_t)(NUM_USERS + pi) * 32 + l;
    size_t noff = (size_t)(NUM_USERS + ni) * 32 + l;

    float2 ue = __ldg(uemb + (size_t)u * 32 + l);
    float2 a1 = __half22float2(__ldg(l1 + uoff));
    float2 a2 = __half22float2(__ldg(l2 + uoff));
    float2 a3 = __half22float2(__ldg(l3 + uoff));
    float2 uf = make_float2(ue.x + a1.x + a2.x + a3.x,
                            ue.y + a1.y + a2.y + a3.y);

    float2 pe = __ldg(iemb + (size_t)pi * 32 + l);
    float2 b1 = __half22float2(__ldg(l1 + poff));
    float2 b2 = __half22float2(__ldg(l2 + poff));
    float2 b3 = __half22float2(__ldg(l3 + poff));
    float2 pf = make_float2(pe.x + b1.x + b2.x + b3.x,
                            pe.y + b1.y + b2.y + b3.y);

    float2 ne = __ldg(iemb + (size_t)ni * 32 + l);
    float2 c1 = __half22float2(__ldg(l1 + noff));
    float2 c2 = __half22float2(__ldg(l2 + noff));
    float2 c3 = __half22float2(__ldg(l3 + noff));
    float2 nf = make_float2(ne.x + c1.x + c2.x + c3.x,
                            ne.y + c1.y + c2.y + c3.y);

    float ps = uf.x * pf.x + uf.y * pf.y;
    float ns = uf.x * nf.x + uf.y * nf.y;
    #pragma unroll
    for (int o = 16; o; o >>= 1) {
        ps += __shfl_xor_sync(0xFFFFFFFFu, ps, o);
        ns += __shfl_xor_sync(0xFFFFFFFFu, ns, o);
    }
    if (l == 0) {
        out[w]         = ps * (1.0f / 16.0f);
        out[batch + w] = ns * (1.0f / 16.0f);
    }
}

// ---------------------------------------------------------------------------
extern "C" void kernel_launch(void* const* d_in, const int* in_sizes, int n_in,
                              void* d_out, int out_size)
{
    const int*   users = (const int*)  d_in[0];
    const int*   pos   = (const int*)  d_in[1];
    const int*   neg   = (const int*)  d_in[2];
    const int*   rows  = (const int*)  d_in[3];
    const int*   cols  = (const int*)  d_in[4];
    const float* vals  = (const float*)d_in[5];
    const float* uemb  = (const float*)d_in[6];
    const float* iemb  = (const float*)d_in[7];
    float* out = (float*)d_out;

    const int n_edges = in_sizes[3];
    const int batch   = in_sizes[0];

    int4 *curH, *l1H, *l2H;
    int2 *l2F8;
    cudaGetSymbolAddress((void**)&curH, g_curH);
    cudaGetSymbolAddress((void**)&l1H,  g_l1H);
    cudaGetSymbolAddress((void**)&l2H,  g_l2H);
    cudaGetSymbolAddress((void**)&l2F8, g_l2F8);

    const int n4 = N_NODES * (EMB / 4);
    const int TB = 256;
    const int n_e4  = (n_edges + 3) / 4;
    const int n_ih  = (n_e4 > n4) ? n_e4 : n4;
    const int grid_ih   = (n_ih + TB - 1) / TB;
    const int grid_scat = (n_e4 + TB - 1) / TB;
    const int grid_spmm = (N_NODES * 8 + TB - 1) / TB;

    // fused init + histogram (4 edges/thread)
    init_hist_kernel<<<grid_ih, TB>>>((const float4*)uemb, (const float4*)iemb,
                                      (uint2*)curH, rows, n_edges);
    // CSR build
    scan1_kernel<<<SCAN_NB, SCAN_BS>>>();
    scan23_kernel<<<SCAN_NB, SCAN_BS>>>(n_edges);
    scatter_kernel<<<grid_scat, TB>>>(rows, cols, vals, n_edges);

    // layers: l1 (fp16), l2 (fp16 + fp8 side copy), l3 (fp8 gather) -> curH
    spmm_h16_kernel<<<grid_spmm, TB>>>(curH, l1H, nullptr);
    spmm_h16_kernel<<<grid_spmm, TB>>>(l1H,  l2H, l2F8);
    spmm_f8_kernel <<<grid_spmm, TB>>>(l2F8, curH);      // curH := l3

    // scores
    const int grid_score = (batch + (TB / 32) - 1) / (TB / 32);
    score_kernel<<<grid_score, TB>>>(users, pos, neg,
                                     (const float2*)uemb, (const float2*)iemb,
                                     (const __half2*)l1H, (const __half2*)l2H,
                                     (const __half2*)curH, out, batch);
}

// round 7
// speedup vs baseline: 1.2211x; 1.2211x over previous
#include <cuda_runtime.h>
#include <cuda_fp16.h>
#include <cstdint>

#define NUM_USERS 100000
#define NUM_ITEMS 50000
#define N_NODES   150000
#define EMB       64
#define BATCH     4096
#define MAX_EDGES 4800000

#define SCAN_BS   1024
#define SCAN_NB   ((N_NODES + SCAN_BS - 1) / SCAN_BS)   // 147

#define F8_SCALE    512.0f
#define F8_INVSCALE (1.0f / 512.0f)

// ---- static scratch (allocation-free) ----
__device__ int4  g_curH [(size_t)N_NODES * 8];   // emb fp16, then reused as l3
__device__ int4  g_l1H  [(size_t)N_NODES * 8];
__device__ int4  g_l2H  [(size_t)N_NODES * 8];
__device__ int2  g_l2F8 [(size_t)N_NODES * 8];   // l2 * 512 in e4m3
__device__ int2  g_edges[MAX_EDGES];             // {col, val as duplicated half2}
__device__ int   g_count[N_NODES];               // zero on entry (BSS / re-zeroed by scan23)
__device__ int   g_rowptr[N_NODES + 1];
__device__ int   g_off[N_NODES];
__device__ int   g_blocksum[SCAN_NB];

static __device__ __forceinline__ unsigned h2bits(__half2 h) {
    return *reinterpret_cast<unsigned*>(&h);
}
static __device__ __forceinline__ __half2 bits2h(unsigned b) {
    return *reinterpret_cast<__half2*>(&b);
}
static __device__ __forceinline__ unsigned short pack_e4m3x2(float lo, float hi) {
    unsigned short s;
    asm("cvt.rn.satfinite.e4m3x2.f32 %0, %1, %2;" : "=h"(s) : "f"(hi), "f"(lo));
    return s;
}
static __device__ __forceinline__ __half2 unpack_e4m3x2_h2(unsigned short s) {
    unsigned hb;
    asm("cvt.rn.f16x2.e4m3x2 %0, %1;" : "=r"(hb) : "h"(s));
    return bits2h(hb);
}

// ---------------------------------------------------------------------------
// fused init + histogram: curH = fp16(emb); 1 edge/thread histogram.
// ---------------------------------------------------------------------------
__global__ void init_hist_kernel(const float4* __restrict__ uemb,
                                 const float4* __restrict__ iemb,
                                 uint2* __restrict__ curH,
                                 const int* __restrict__ rows,
                                 int n_edges)
{
    const int n4      = N_NODES * (EMB / 4);
    const int n4_user = NUM_USERS * (EMB / 4);
    int i = blockIdx.x * blockDim.x + threadIdx.x;
    if (i < n4) {
        float4 v = (i < n4_user) ? __ldg(uemb + i) : __ldg(iemb + i - n4_user);
        uint2 c;
        c.x = h2bits(__floats2half2_rn(v.x, v.y));
        c.y = h2bits(__floats2half2_rn(v.z, v.w));
        curH[i] = c;
    }
    if (i < n_edges) atomicAdd(&g_count[__ldg(rows + i)], 1);
}

// ---------------------------------------------------------------------------
// scan1: per-block sums of g_count
// ---------------------------------------------------------------------------
__global__ void scan1_kernel()
{
    int idx = blockIdx.x * SCAN_BS + threadIdx.x;
    int c = (idx < N_NODES) ? g_count[idx] : 0;
    int lane = threadIdx.x & 31, wid = threadIdx.x >> 5;
    #pragma unroll
    for (int o = 16; o; o >>= 1) c += __shfl_down_sync(0xFFFFFFFFu, c, o);
    __shared__ int ws[32];
    if (lane == 0) ws[wid] = c;
    __syncthreads();
    if (wid == 0) {
        c = ws[lane];
        #pragma unroll
        for (int o = 16; o; o >>= 1) c += __shfl_down_sync(0xFFFFFFFFu, c, o);
        if (lane == 0) g_blocksum[blockIdx.x] = c;
    }
}

// ---------------------------------------------------------------------------
// scan23: redundant block-sum scan per block + local exclusive scan.
// Writes rowptr + off; re-zeros g_count for the next replay.
// ---------------------------------------------------------------------------
__global__ void scan23_kernel(int n_edges)
{
    __shared__ int bs[256];
    __shared__ int ws[32];

    int t = threadIdx.x;
    if (t < 256) bs[t] = (t < SCAN_NB) ? g_blocksum[t] : 0;
    __syncthreads();
    #pragma unroll
    for (int off = 1; off < 256; off <<= 1) {
        int x = 0;
        if (t < 256 && t >= off) x = bs[t - off];
        __syncthreads();
        if (t < 256) bs[t] += x;
        __syncthreads();
    }
    int blockoff = (blockIdx.x == 0) ? 0 : bs[blockIdx.x - 1];

    int idx = blockIdx.x * SCAN_BS + t;
    int c = (idx < N_NODES) ? g_count[idx] : 0;
    int lane = t & 31, wid = t >> 5;
    int v = c;
    #pragma unroll
    for (int o = 1; o < 32; o <<= 1) {
        int s = __shfl_up_sync(0xFFFFFFFFu, v, o);
        if (lane >= o) v += s;
    }
    if (lane == 31) ws[wid] = v;
    __syncthreads();
    if (wid == 0) {
        int orig = ws[lane];
        int s = orig;
        #pragma unroll
        for (int o = 1; o < 32; o <<= 1) {
            int x = __shfl_up_sync(0xFFFFFFFFu, s, o);
            if (lane >= o) s += x;
        }
        ws[lane] = s - orig;
    }
    __syncthreads();
    int excl = (v - c) + ws[wid] + blockoff;
    if (idx < N_NODES) {
        g_rowptr[idx] = excl;
        g_off[idx]    = excl;
        g_count[idx]  = 0;
    }
    if (idx == 0) g_rowptr[N_NODES] = n_edges;
}

// ---------------------------------------------------------------------------
// scatter: 1 edge/thread (r5 shape — ILP variant regressed).
// Edge payload: {col, val duplicated as half2} so SpMM needs zero conversion.
// ---------------------------------------------------------------------------
__global__ void scatter_kernel(const int* __restrict__ rows,
                               const int* __restrict__ cols,
                               const float* __restrict__ vals, int n)
{
    int i = blockIdx.x * blockDim.x + threadIdx.x;
    if (i >= n) return;
    int   row = __ldg(rows + i);
    float v   = __ldg(vals + i);
    unsigned hv = h2bits(__floats2half2_rn(v, v));
    int pos = atomicAdd(&g_off[row], 1);
    g_edges[pos] = make_int2(__ldg(cols + i), (int)hv);
}

// ---------------------------------------------------------------------------
// CSR SpMM, fp16 src, pure HFMA2: 8 lanes per row, lane owns 8 features.
// Inner loop: 1 LDG.128 + 2 SHFL + 4 HFMA2 per thread-edge.
// Optionally emits an e4m3 (x F8_SCALE) copy of the output.
// ---------------------------------------------------------------------------
__global__ void spmm_h16_kernel(const int4* __restrict__ src,
                                int4* __restrict__ dst,
                                int2* __restrict__ dstF8)
{
    int t = blockIdx.x * blockDim.x + threadIdx.x;
    int g = t >> 3;
    int l = t & 7;
    if (g >= N_NODES) return;
    unsigned gmask = 0xFFu << (threadIdx.x & 24);

    int start = __ldg(&g_rowptr[g]);
    int end   = __ldg(&g_rowptr[g + 1]);

    __half2 z  = __float2half2_rn(0.f);
    __half2 a0 = z, a1 = z, a2 = z, a3 = z;

    int base = start;
    for (; base + 8 <= end; base += 8) {
        int2 e = __ldg(&g_edges[base + l]);
        #pragma unroll
        for (int k = 0; k < 8; k++) {
            int      col = __shfl_sync(gmask, e.x, k, 8);
            __half2  v2  = bits2h((unsigned)__shfl_sync(gmask, e.y, k, 8));
            int4 q = __ldg(&src[(size_t)col * 8 + l]);
            a0 = __hfma2(v2, bits2h((unsigned)q.x), a0);
            a1 = __hfma2(v2, bits2h((unsigned)q.y), a1);
            a2 = __hfma2(v2, bits2h((unsigned)q.z), a2);
            a3 = __hfma2(v2, bits2h((unsigned)q.w), a3);
        }
    }
    int rem = end - base;
    if (rem > 0) {
        int2 e = (l < rem) ? __ldg(&g_edges[base + l]) : make_int2(0, 0);
        for (int k = 0; k < rem; k++) {
            int      col = __shfl_sync(gmask, e.x, k, 8);
            __half2  v2  = bits2h((unsigned)__shfl_sync(gmask, e.y, k, 8));
            int4 q = __ldg(&src[(size_t)col * 8 + l]);
            a0 = __hfma2(v2, bits2h((unsigned)q.x), a0);
            a1 = __hfma2(v2, bits2h((unsigned)q.y), a1);
            a2 = __hfma2(v2, bits2h((unsigned)q.z), a2);
            a3 = __hfma2(v2, bits2h((unsigned)q.w), a3);
        }
    }

    int4 o;
    o.x = (int)h2bits(a0);
    o.y = (int)h2bits(a1);
    o.z = (int)h2bits(a2);
    o.w = (int)h2bits(a3);
    dst[(size_t)g * 8 + l] = o;

    if (dstF8) {
        float2 f0 = __half22float2(a0);
        float2 f1 = __half22float2(a1);
        float2 f2 = __half22float2(a2);
        float2 f3 = __half22float2(a3);
        unsigned short s0 = pack_e4m3x2(f0.x * F8_SCALE, f0.y * F8_SCALE);
        unsigned short s1 = pack_e4m3x2(f1.x * F8_SCALE, f1.y * F8_SCALE);
        unsigned short s2 = pack_e4m3x2(f2.x * F8_SCALE, f2.y * F8_SCALE);
        unsigned short s3 = pack_e4m3x2(f3.x * F8_SCALE, f3.y * F8_SCALE);
        int2 p;
        p.x = (unsigned)s0 | ((unsigned)s1 << 16);
        p.y = (unsigned)s2 | ((unsigned)s3 << 16);
        dstF8[(size_t)g * 8 + l] = p;
    }
}

// ---------------------------------------------------------------------------
// CSR SpMM, e4m3 src (pre-scaled by F8_SCALE): 64B gathers, half2 accumulate
// (scaled domain keeps magnitudes ~0.05, well inside fp16), fp16 out.
// ---------------------------------------------------------------------------
__global__ void spmm_f8_kernel(const int2* __restrict__ srcF8,
                               int4* __restrict__ dst)
{
    int t = blockIdx.x * blockDim.x + threadIdx.x;
    int g = t >> 3;
    int l = t & 7;
    if (g >= N_NODES) return;
    unsigned gmask = 0xFFu << (threadIdx.x & 24);

    int start = __ldg(&g_rowptr[g]);
    int end   = __ldg(&g_rowptr[g + 1]);

    __half2 z  = __float2half2_rn(0.f);
    __half2 a0 = z, a1 = z, a2 = z, a3 = z;

    int base = start;
    for (; base + 8 <= end; base += 8) {
        int2 e = __ldg(&g_edges[base + l]);
        #pragma unroll
        for (int k = 0; k < 8; k++) {
            int      col = __shfl_sync(gmask, e.x, k, 8);
            __half2  v2  = bits2h((unsigned)__shfl_sync(gmask, e.y, k, 8));
            int2 q = __ldg(&srcF8[(size_t)col * 8 + l]);
            a0 = __hfma2(v2, unpack_e4m3x2_h2((unsigned short)(q.x & 0xFFFF)), a0);
            a1 = __hfma2(v2, unpack_e4m3x2_h2((unsigned short)((unsigned)q.x >> 16)), a1);
            a2 = __hfma2(v2, unpack_e4m3x2_h2((unsigned short)(q.y & 0xFFFF)), a2);
            a3 = __hfma2(v2, unpack_e4m3x2_h2((unsigned short)((unsigned)q.y >> 16)), a3);
        }
    }
    int rem = end - base;
    if (rem > 0) {
        int2 e = (l < rem) ? __ldg(&g_edges[base + l]) : make_int2(0, 0);
        for (int k = 0; k < rem; k++) {
            int      col = __shfl_sync(gmask, e.x, k, 8);
            __half2  v2  = bits2h((unsigned)__shfl_sync(gmask, e.y, k, 8));
            int2 q = __ldg(&srcF8[(size_t)col * 8 + l]);
            a0 = __hfma2(v2, unpack_e4m3x2_h2((unsigned short)(q.x & 0xFFFF)), a0);
            a1 = __hfma2(v2, unpack_e4m3x2_h2((unsigned short)((unsigned)q.x >> 16)), a1);
            a2 = __hfma2(v2, unpack_e4m3x2_h2((unsigned short)(q.y & 0xFFFF)), a2);
            a3 = __hfma2(v2, unpack_e4m3x2_h2((unsigned short)((unsigned)q.y >> 16)), a3);
        }
    }

    // descale in fp32 epilogue, round once to fp16
    float2 f0 = __half22float2(a0);
    float2 f1 = __half22float2(a1);
    float2 f2 = __half22float2(a2);
    float2 f3 = __half22float2(a3);
    int4 o;
    o.x = (int)h2bits(__floats2half2_rn(f0.x * F8_INVSCALE, f0.y * F8_INVSCALE));
    o.y = (int)h2bits(__floats2half2_rn(f1.x * F8_INVSCALE, f1.y * F8_INVSCALE));
    o.z = (int)h2bits(__floats2half2_rn(f2.x * F8_INVSCALE, f2.y * F8_INVSCALE));
    o.w = (int)h2bits(__floats2half2_rn(f3.x * F8_INVSCALE, f3.y * F8_INVSCALE));
    dst[(size_t)g * 8 + l] = o;
}

// ---------------------------------------------------------------------------
// scoring: one warp per batch element; exact fp32 emb + fp16 layer terms.
// ---------------------------------------------------------------------------
__global__ void score_kernel(const int* __restrict__ users,
                             const int* __restrict__ pos_items,
                             const int* __restrict__ neg_items,
                             const float2* __restrict__ uemb,
                             const float2* __restrict__ iemb,
                             const __half2* __restrict__ l1,
                             const __half2* __restrict__ l2,
                             const __half2* __restrict__ l3,
                             float* __restrict__ out,
                             int batch)
{
    int w = (blockIdx.x * blockDim.x + threadIdx.x) >> 5;
    int l = threadIdx.x & 31;
    if (w >= batch) return;

    int u  = __ldg(users + w);
    int pi = __ldg(pos_items + w);
    int ni = __ldg(neg_items + w);

    size_t uoff = (size_t)u * 32 + l;
    size_t poff = (size_t)(NUM_USERS + pi) * 32 + l;
    size_t noff = (size_t)(NUM_USERS + ni) * 32 + l;

    float2 ue = __ldg(uemb + (size_t)u * 32 + l);
    float2 a1 = __half22float2(__ldg(l1 + uoff));
    float2 a2 = __half22float2(__ldg(l2 + uoff));
    float2 a3 = __half22float2(__ldg(l3 + uoff));
    float2 uf = make_float2(ue.x + a1.x + a2.x + a3.x,
                            ue.y + a1.y + a2.y + a3.y);

    float2 pe = __ldg(iemb + (size_t)pi * 32 + l);
    float2 b1 = __half22float2(__ldg(l1 + poff));
    float2 b2 = __half22float2(__ldg(l2 + poff));
    float2 b3 = __half22float2(__ldg(l3 + poff));
    float2 pf = make_float2(pe.x + b1.x + b2.x + b3.x,
                            pe.y + b1.y + b2.y + b3.y);

    float2 ne = __ldg(iemb + (size_t)ni * 32 + l);
    float2 c1 = __half22float2(__ldg(l1 + noff));
    float2 c2 = __half22float2(__ldg(l2 + noff));
    float2 c3 = __half22float2(__ldg(l3 + noff));
    float2 nf = make_float2(ne.x + c1.x + c2.x + c3.x,
                            ne.y + c1.y + c2.y + c3.y);

    float ps = uf.x * pf.x + uf.y * pf.y;
    float ns = uf.x * nf.x + uf.y * nf.y;
    #pragma unroll
    for (int o = 16; o; o >>= 1) {
        ps += __shfl_xor_sync(0xFFFFFFFFu, ps, o);
        ns += __shfl_xor_sync(0xFFFFFFFFu, ns, o);
    }
    if (l == 0) {
        out[w]         = ps * (1.0f / 16.0f);
        out[batch + w] = ns * (1.0f / 16.0f);
    }
}

// ---------------------------------------------------------------------------
extern "C" void kernel_launch(void* const* d_in, const int* in_sizes, int n_in,
                              void* d_out, int out_size)
{
    const int*   users = (const int*)  d_in[0];
    const int*   pos   = (const int*)  d_in[1];
    const int*   neg   = (const int*)  d_in[2];
    const int*   rows  = (const int*)  d_in[3];
    const int*   cols  = (const int*)  d_in[4];
    const float* vals  = (const float*)d_in[5];
    const float* uemb  = (const float*)d_in[6];
    const float* iemb  = (const float*)d_in[7];
    float* out = (float*)d_out;

    const int n_edges = in_sizes[3];
    const int batch   = in_sizes[0];

    int4 *curH, *l1H, *l2H;
    int2 *l2F8;
    cudaGetSymbolAddress((void**)&curH, g_curH);
    cudaGetSymbolAddress((void**)&l1H,  g_l1H);
    cudaGetSymbolAddress((void**)&l2H,  g_l2H);
    cudaGetSymbolAddress((void**)&l2F8, g_l2F8);

    const int n4 = N_NODES * (EMB / 4);
    const int TB = 256;
    const int n_ih  = (n_edges > n4) ? n_edges : n4;
    const int grid_ih   = (n_ih + TB - 1) / TB;
    const int grid_edge = (n_edges + TB - 1) / TB;
    const int grid_spmm = (N_NODES * 8 + TB - 1) / TB;

    // fused init + histogram
    init_hist_kernel<<<grid_ih, TB>>>((const float4*)uemb, (const float4*)iemb,
                                      (uint2*)curH, rows, n_edges);
    // CSR build
    scan1_kernel<<<SCAN_NB, SCAN_BS>>>();
    scan23_kernel<<<SCAN_NB, SCAN_BS>>>(n_edges);
    scatter_kernel<<<grid_edge, TB>>>(rows, cols, vals, n_edges);

    // layers: l1 (fp16), l2 (fp16 + fp8 side copy), l3 (fp8 gather) -> curH
    spmm_h16_kernel<<<grid_spmm, TB>>>(curH, l1H, nullptr);
    spmm_h16_kernel<<<grid_spmm, TB>>>(l1H,  l2H, l2F8);
    spmm_f8_kernel <<<grid_spmm, TB>>>(l2F8, curH);      // curH := l3

    // scores
    const int grid_score = (batch + (TB / 32) - 1) / (TB / 32);
    score_kernel<<<grid_score, TB>>>(users, pos, neg,
                                     (const float2*)uemb, (const float2*)iemb,
                                     (const __half2*)l1H, (const __half2*)l2H,
                                     (const __half2*)curH, out, batch);
}